// round 15
// baseline (speedup 1.0000x reference)
#include <cuda_runtime.h>

// SparseBPNeuralNetwork — fused sparse BP decoder, round 15.
// Software-pipelined var/check phases: ROWS=4 as two staggered float2
// pipelines (A = rows b,b+1; B = rows b+2,b+3). Every barrier region mixes
// one MUFU-heavy var phase with one crossbar-heavy check phase so the MUFU
// and shared-crossbar floors overlap instead of serializing.

#define NV 648
#define NE 1944
#define BATCH 2048
#define NCHK 324
#define TOT ((size_t)BATCH * NV)
#define ROWS 4
#define THREADS NV

#define LOG2E 1.4426950408889634f
#define LN2F  0.69314718055994531f
#define VC2   24.52612f        // 17 * log2(e): keeps products finite
#define TL2   20.9315735f      // log2(1.999999/1e-6) == 2*atanh(0.999999)/ln2

// dynamic smem: [s_eA | s_tlA | s_eB | s_tlB], each NV*3 float2
#define SLOTS (NV * 3)
#define SMEM_BYTES (4 * SLOTS * (int)sizeof(float2))

// ---- preprocessed graph/weight data ----
__device__ int    g_eov[SLOTS];      // slot (var,layer) -> edge
__device__ int    g_slot[NE];        // edge -> slot (var*3 + layer)
__device__ float2 g_ws[4][SLOTS];    // per VN layer, per slot: (w_(l+1)%3, w_(l+2)%3)
__device__ float  g_w9[NV][3];       // output weights per var (3 slots)

// ---------------- preprocessing ----------------
#define SCAN4 (NV * NE / 4)

__global__ void prep1(const float4* __restrict__ M_out4) {
    int idx = blockIdx.x * blockDim.x + threadIdx.x;     // over NV*NE/4
    if (idx >= SCAN4) return;
    float4 val = M_out4[idx];
    if (val.x == 0.0f && val.y == 0.0f && val.z == 0.0f && val.w == 0.0f) return;
    int lin = idx * 4;
    int v = lin / NE;
    int e = lin - v * NE;
    float vv[4] = {val.x, val.y, val.z, val.w};
#pragma unroll
    for (int k = 0; k < 4; k++) {
        if (vv[k] != 0.0f) {
            int ek = e + k;
            int s  = v * 3 + ek / NV;       // layer = ek / NV
            g_slot[ek] = s;
            g_eov[s]   = ek;
        }
    }
}

__global__ void prep2(const float* __restrict__ W1, const float* __restrict__ W3,
                      const float* __restrict__ W5, const float* __restrict__ W7,
                      const float* __restrict__ W9) {
    int idx = blockIdx.x * blockDim.x + threadIdx.x;     // over 12*NV
    if (idx < 12 * NV) {
        int li = idx / SLOTS;
        int s  = idx - li * SLOTS;
        int v  = s / 3;
        int l  = s - v * 3;
        int e   = g_eov[s];
        int j1e = g_eov[v * 3 + ((l + 1) % 3)];
        int j2e = g_eov[v * 3 + ((l + 2) % 3)];
        const float* W = (li == 0) ? W1 : (li == 1) ? W3 : (li == 2) ? W5 : W7;
        g_ws[li][s] = make_float2(W[(size_t)e * NE + j1e], W[(size_t)e * NE + j2e]);
    }
    if (idx < 3 * NV) {
        int v = idx / 3;
        int k = idx - v * 3;
        g_w9[v][k] = W9[(size_t)v * NE + g_eov[v * 3 + k]];
    }
}

// ---------------- fast math ----------------
__device__ __forceinline__ float sigmoidf(float s) {
    return __fdividef(1.0f, 1.0f + __expf(-s));
}

// Half-check CN: this thread owns 3 of a check's 6 edges (partner = lane^1).
__device__ __forceinline__ void cn_half(unsigned mask, const float2 ev[3], float2 tl[3]) {
    float2 n[3], d[3];
#pragma unroll
    for (int k = 0; k < 3; k++) {
        n[k] = make_float2(ev[k].x - 1.0f, ev[k].y - 1.0f);
        d[k] = make_float2(ev[k].x + 1.0f, ev[k].y + 1.0f);
    }
    float2 n01 = make_float2(n[0].x * n[1].x, n[0].y * n[1].y);
    float2 n12 = make_float2(n[1].x * n[2].x, n[1].y * n[2].y);
    float2 n02 = make_float2(n[0].x * n[2].x, n[0].y * n[2].y);
    float2 d01 = make_float2(d[0].x * d[1].x, d[0].y * d[1].y);
    float2 d12 = make_float2(d[1].x * d[2].x, d[1].y * d[2].y);
    float2 d02 = make_float2(d[0].x * d[2].x, d[0].y * d[2].y);
    float pnx = n01.x * n[2].x, pny = n01.y * n[2].y;
    float pdx = d01.x * d[2].x, pdy = d01.y * d[2].y;
    float onx = __shfl_xor_sync(mask, pnx, 1);
    float ony = __shfl_xor_sync(mask, pny, 1);
    float odx = __shfl_xor_sync(mask, pdx, 1);
    float ody = __shfl_xor_sync(mask, pdy, 1);
    float2 qn[3] = {n12, n02, n01};
    float2 qd[3] = {d12, d02, d01};
#pragma unroll
    for (int k = 0; k < 3; k++) {
        float Px = qn[k].x * onx, Qx = qd[k].x * odx;
        float Py = qn[k].y * ony, Qy = qd[k].y * ody;
        float nx = fmaxf(Qx + Px, 1e-33f), dx = fmaxf(Qx - Px, 1e-33f);
        float ny = fmaxf(Qy + Py, 1e-33f), dy = fmaxf(Qy - Py, 1e-33f);
        float tx = __log2f(nx) - __log2f(dx);
        float ty = __log2f(ny) - __log2f(dy);
        tl[k].x = fminf(fmaxf(tx, -TL2), TL2);
        tl[k].y = fminf(fmaxf(ty, -TL2), TL2);
    }
}

// check phase for one pipeline: 3 random LDS.64 + 3 random STS.64
__device__ __forceinline__ void check_phase(unsigned mask, int sl0, int sl1, int sl2,
                                            const float2* s_e, float2* s_tl) {
    float2 ev[3], tl[3];
    ev[0] = s_e[sl0]; ev[1] = s_e[sl1]; ev[2] = s_e[sl2];
    cn_half(mask, ev, tl);
    s_tl[sl0] = tl[0]; s_tl[sl1] = tl[1]; s_tl[sl2] = tl[2];
}

// var phase for one pipeline: outputs + next-iteration exps, all contiguous
__device__ __forceinline__ void var_phase(int li, int tid, size_t brow,
                                          float2 llr, float2 llr2,
                                          const float2* s_tl, float2* s_e,
                                          float* __restrict__ out) {
    float2 t0 = s_tl[3 * tid], t1 = s_tl[3 * tid + 1], t2 = s_tl[3 * tid + 2];
    if (li < 4) {
        size_t off = (size_t)(4 - li) * TOT + brow * NV;
        out[off + tid]      = sigmoidf(fmaf(LN2F, t0.x + t1.x + t2.x, llr.x));
        out[off + NV + tid] = sigmoidf(fmaf(LN2F, t0.y + t1.y + t2.y, llr.y));
        float2 w0 = g_ws[li][3 * tid];
        float2 w1 = g_ws[li][3 * tid + 1];
        float2 w2 = g_ws[li][3 * tid + 2];
        float2 e0, e1, e2v;
        e0.x  = exp2f(fminf(fmaf(w0.x, t1.x, fmaf(w0.y, t2.x, llr2.x)), VC2));
        e0.y  = exp2f(fminf(fmaf(w0.x, t1.y, fmaf(w0.y, t2.y, llr2.y)), VC2));
        e1.x  = exp2f(fminf(fmaf(w1.x, t2.x, fmaf(w1.y, t0.x, llr2.x)), VC2));
        e1.y  = exp2f(fminf(fmaf(w1.x, t2.y, fmaf(w1.y, t0.y, llr2.y)), VC2));
        e2v.x = exp2f(fminf(fmaf(w2.x, t0.x, fmaf(w2.y, t1.x, llr2.x)), VC2));
        e2v.y = exp2f(fminf(fmaf(w2.x, t0.y, fmaf(w2.y, t1.y, llr2.y)), VC2));
        s_e[3 * tid]     = e0;
        s_e[3 * tid + 1] = e1;
        s_e[3 * tid + 2] = e2v;
    } else {
        float w90 = g_w9[tid][0], w91 = g_w9[tid][1], w92 = g_w9[tid][2];
        size_t off = brow * NV;
        float sx = w90 * t0.x + w91 * t1.x + w92 * t2.x;
        float sy = w90 * t0.y + w91 * t1.y + w92 * t2.y;
        out[off + tid]      = sigmoidf(fmaf(LN2F, sx, llr.x));
        out[off + NV + tid] = sigmoidf(fmaf(LN2F, sy, llr.y));
    }
}

__device__ __forceinline__ void var_init(int tid, float2 llr2, float2* s_e) {
    float2 e2;
    e2.x = exp2f(fminf(llr2.x, VC2));
    e2.y = exp2f(fminf(llr2.y, VC2));
    s_e[3 * tid]     = e2;
    s_e[3 * tid + 1] = e2;
    s_e[3 * tid + 2] = e2;
}

__global__ __launch_bounds__(THREADS, 2)
void bp_main(const float* __restrict__ x, float* __restrict__ out) {
    extern __shared__ float2 smem[];
    float2* s_eA  = smem;
    float2* s_tlA = smem + SLOTS;
    float2* s_eB  = smem + 2 * SLOTS;
    float2* s_tlB = smem + 3 * SLOTS;

    const size_t bA = (size_t)blockIdx.x * ROWS;      // pipeline A: rows bA, bA+1
    const size_t bB = bA + 2;                          // pipeline B: rows bA+2, bA+3
    const int tid = threadIdx.x;
    // 648 = 20 full warps + 8 lanes; partner (lane^1) always inside the mask
    const unsigned mask = (tid >= 640) ? 0xffu : 0xffffffffu;

    // channel LLRs for both pipelines (coalesced)
    float2 llrA, llrB;
    llrA.x = x[bA * NV + tid];
    llrA.y = x[(bA + 1) * NV + tid];
    llrB.x = x[bB * NV + tid];
    llrB.y = x[(bB + 1) * NV + tid];
    const float2 llr2A = make_float2(llrA.x * LOG2E, llrA.y * LOG2E);
    const float2 llr2B = make_float2(llrB.x * LOG2E, llrB.y * LOG2E);

    // check-role slots (check c = tid>>1, half h = tid&1)
    const int ebase = (tid >> 1) * 6 + (tid & 1) * 3;
    const int sl0 = g_slot[ebase], sl1 = g_slot[ebase + 1], sl2 = g_slot[ebase + 2];

    // R0: A init
    var_init(tid, llr2A, s_eA);
    __syncthreads();

    // R1: checkA(0) | B init
    check_phase(mask, sl0, sl1, sl2, s_eA, s_tlA);
    var_init(tid, llr2B, s_eB);
    __syncthreads();

    // R2..R9: staggered main loop
#pragma unroll
    for (int li = 0; li < 4; li++) {
        // varA(li) | checkB(li)
        var_phase(li, tid, bA, llrA, llr2A, s_tlA, s_eA, out);
        check_phase(mask, sl0, sl1, sl2, s_eB, s_tlB);
        __syncthreads();
        // checkA(li+1) | varB(li)
        check_phase(mask, sl0, sl1, sl2, s_eA, s_tlA);
        var_phase(li, tid, bB, llrB, llr2B, s_tlB, s_eB, out);
        __syncthreads();
    }

    // R10: varA(4 final) | checkB(4)
    var_phase(4, tid, bA, llrA, llr2A, s_tlA, s_eA, out);
    check_phase(mask, sl0, sl1, sl2, s_eB, s_tlB);
    __syncthreads();

    // R11: varB(4 final)
    var_phase(4, tid, bB, llrB, llr2B, s_tlB, s_eB, out);
}

// ---------------- launch ----------------
extern "C" void kernel_launch(void* const* d_in, const int* in_sizes, int n_in,
                              void* d_out, int out_size) {
    // metadata order: x, M_first, M_cn, M_out, bias_matrix, W1, W3, W5, W7, W9, B0..B4
    const float* x     = (const float*)d_in[0];
    const float* M_out = (const float*)d_in[3];
    const float* W1    = (const float*)d_in[5];
    const float* W3    = (const float*)d_in[6];
    const float* W5    = (const float*)d_in[7];
    const float* W7    = (const float*)d_in[8];
    const float* W9    = (const float*)d_in[9];

    cudaFuncSetAttribute(bp_main, cudaFuncAttributeMaxDynamicSharedMemorySize,
                         SMEM_BYTES);

    prep1<<<(SCAN4 + 255) / 256, 256>>>((const float4*)M_out);
    prep2<<<(12 * NV + 255) / 256, 256>>>(W1, W3, W5, W7, W9);
    bp_main<<<BATCH / ROWS, THREADS, SMEM_BYTES>>>(x, (float*)d_out);
}

// round 16
// speedup vs baseline: 1.0092x; 1.0092x over previous
#include <cuda_runtime.h>

// SparseBPNeuralNetwork — fused sparse BP decoder, round 16.
// Round 14 structure + packed f32x2 math: both batch rows of every product /
// sum / VN-FMA execute as ONE fma.rn.f32x2-class instruction (sm_103a packed
// pipe, PTX-only). FMA-pipe work ~halves; MUFU & crossbar unchanged.

#define NV 648
#define NE 1944
#define BATCH 2048
#define NCHK 324
#define TOT ((size_t)BATCH * NV)
#define ROWS 2
#define THREADS NV

#define LOG2E 1.4426950408889634f
#define LN2F  0.69314718055994531f
#define VC2   24.52612f        // 17 * log2(e): keeps products finite
#define TL2   20.9315735f      // log2(1.999999/1e-6) == 2*atanh(0.999999)/ln2

#define SLOTS (NV * 3)

typedef unsigned long long u64;

// ---- preprocessed graph/weight data ----
__device__ int    g_eov[SLOTS];      // slot (var,layer) -> edge
__device__ int    g_slot[NE];        // edge -> slot (var*3 + layer)
__device__ float2 g_ws[4][SLOTS];    // per VN layer, per slot: (w_(l+1)%3, w_(l+2)%3)
__device__ float  g_w9[NV][3];       // output weights per var (3 slots)

// ---------------- preprocessing ----------------
#define SCAN4 (NV * NE / 4)

__global__ void prep1(const float4* __restrict__ M_out4) {
    int idx = blockIdx.x * blockDim.x + threadIdx.x;     // over NV*NE/4
    if (idx >= SCAN4) return;
    float4 val = M_out4[idx];
    if (val.x == 0.0f && val.y == 0.0f && val.z == 0.0f && val.w == 0.0f) return;
    int lin = idx * 4;
    int v = lin / NE;
    int e = lin - v * NE;
    float vv[4] = {val.x, val.y, val.z, val.w};
#pragma unroll
    for (int k = 0; k < 4; k++) {
        if (vv[k] != 0.0f) {
            int ek = e + k;
            int s  = v * 3 + ek / NV;       // layer = ek / NV
            g_slot[ek] = s;
            g_eov[s]   = ek;
        }
    }
}

__global__ void prep2(const float* __restrict__ W1, const float* __restrict__ W3,
                      const float* __restrict__ W5, const float* __restrict__ W7,
                      const float* __restrict__ W9) {
    int idx = blockIdx.x * blockDim.x + threadIdx.x;     // over 12*NV
    if (idx < 12 * NV) {
        int li = idx / SLOTS;
        int s  = idx - li * SLOTS;
        int v  = s / 3;
        int l  = s - v * 3;
        int e   = g_eov[s];
        int j1e = g_eov[v * 3 + ((l + 1) % 3)];
        int j2e = g_eov[v * 3 + ((l + 2) % 3)];
        const float* W = (li == 0) ? W1 : (li == 1) ? W3 : (li == 2) ? W5 : W7;
        g_ws[li][s] = make_float2(W[(size_t)e * NE + j1e], W[(size_t)e * NE + j2e]);
    }
    if (idx < 3 * NV) {
        int v = idx / 3;
        int k = idx - v * 3;
        g_w9[v][k] = W9[(size_t)v * NE + g_eov[v * 3 + k]];
    }
}

// ---------------- packed f32x2 helpers ----------------
__device__ __forceinline__ u64 pk(float lo, float hi) {
    u64 r; asm("mov.b64 %0, {%1, %2};" : "=l"(r) : "f"(lo), "f"(hi)); return r;
}
__device__ __forceinline__ void upk(u64 v, float& lo, float& hi) {
    asm("mov.b64 {%0, %1}, %2;" : "=f"(lo), "=f"(hi) : "l"(v));
}
__device__ __forceinline__ u64 mul2(u64 a, u64 b) {
    u64 r; asm("mul.rn.f32x2 %0, %1, %2;" : "=l"(r) : "l"(a), "l"(b)); return r;
}
__device__ __forceinline__ u64 add2(u64 a, u64 b) {
    u64 r; asm("add.rn.f32x2 %0, %1, %2;" : "=l"(r) : "l"(a), "l"(b)); return r;
}
__device__ __forceinline__ u64 fma2(u64 a, u64 b, u64 c) {
    u64 r; asm("fma.rn.f32x2 %0, %1, %2, %3;" : "=l"(r) : "l"(a), "l"(b), "l"(c)); return r;
}

#define ONE2  0x3F8000003F800000ull   // (1.0f, 1.0f)
#define NEG2  0xBF800000BF800000ull   // (-1.0f, -1.0f)

__device__ __forceinline__ float sigmoidf(float s) {
    return __fdividef(1.0f, 1.0f + __expf(-s));
}

// one extrinsic message: P = qn*on, Q = qd*od; tl = clamp(log2((Q+P)/(Q-P)))
__device__ __forceinline__ u64 tl_calc(u64 qn, u64 qd, u64 on, u64 od) {
    u64 P = mul2(qn, on), Q = mul2(qd, od);
    u64 num = add2(Q, P);
    u64 den = fma2(P, NEG2, Q);          // Q - P
    float nx, ny, dx, dy;
    upk(num, nx, ny); upk(den, dx, dy);
    float tx = __log2f(fmaxf(nx, 1e-33f)) - __log2f(fmaxf(dx, 1e-33f));
    float ty = __log2f(fmaxf(ny, 1e-33f)) - __log2f(fmaxf(dy, 1e-33f));
    tx = fminf(fmaxf(tx, -TL2), TL2);
    ty = fminf(fmaxf(ty, -TL2), TL2);
    return pk(tx, ty);
}

// Half-check CN (3 of 6 edges; partner = lane^1), fully packed.
__device__ __forceinline__ void cn_half_pk(unsigned mask, u64 ev0, u64 ev1, u64 ev2,
                                           u64& tl0, u64& tl1, u64& tl2) {
    u64 n0 = add2(ev0, NEG2), n1 = add2(ev1, NEG2), n2 = add2(ev2, NEG2);
    u64 d0 = add2(ev0, ONE2), d1 = add2(ev1, ONE2), d2 = add2(ev2, ONE2);
    u64 n01 = mul2(n0, n1), n12 = mul2(n1, n2), n02 = mul2(n0, n2);
    u64 d01 = mul2(d0, d1), d12 = mul2(d1, d2), d02 = mul2(d0, d2);
    u64 pn = mul2(n01, n2), pd = mul2(d01, d2);       // own 3-products
    u64 on = __shfl_xor_sync(mask, pn, 1);             // partner's 3-products
    u64 od = __shfl_xor_sync(mask, pd, 1);
    tl0 = tl_calc(n12, d12, on, od);
    tl1 = tl_calc(n02, d02, on, od);
    tl2 = tl_calc(n01, d01, on, od);
}

__global__ __launch_bounds__(THREADS, 2)
void bp_main(const float* __restrict__ x, float* __restrict__ out) {
    __shared__ u64 s_e[SLOTS];       // exp2(vin) per slot (rows 0,1 packed)
    __shared__ u64 s_tl[SLOTS];      // log2-domain messages per slot

    const size_t b0  = (size_t)blockIdx.x * ROWS;
    const int tid = threadIdx.x;     // var role: v = tid; check role: half-check
    // 648 = 20 full warps + 8 lanes; partner (lane^1) always inside the mask
    const unsigned mask = (tid >= 640) ? 0xffu : 0xffffffffu;

    // channel LLRs (coalesced)
    const float llrx = x[b0 * NV + tid];
    const float llry = x[(b0 + 1) * NV + tid];
    const u64 llrp  = pk(llrx, llry);
    const u64 llr2p = pk(llrx * LOG2E, llry * LOG2E);
    const u64 ln2p  = pk(LN2F, LN2F);

    // check-role slots (check c = tid>>1, half h = tid&1)
    const int ebase = (tid >> 1) * 6 + (tid & 1) * 3;
    const int sl0 = g_slot[ebase], sl1 = g_slot[ebase + 1], sl2 = g_slot[ebase + 2];

    // ---- iteration-1 var phase: vin = llr for all 3 edges ----
    {
        float ex = exp2f(fminf(llrx * LOG2E, VC2));
        float ey = exp2f(fminf(llry * LOG2E, VC2));
        u64 e2 = pk(ex, ey);
        s_e[3 * tid] = e2; s_e[3 * tid + 1] = e2; s_e[3 * tid + 2] = e2;
    }
    __syncthreads();

#pragma unroll
    for (int li = 0; li < 5; li++) {
        // ---- check phase: 3 random LDS.64 + 3 random STS.64 ----
        {
            u64 tl0, tl1, tl2;
            cn_half_pk(mask, s_e[sl0], s_e[sl1], s_e[sl2], tl0, tl1, tl2);
            s_tl[sl0] = tl0; s_tl[sl1] = tl1; s_tl[sl2] = tl2;
        }
        __syncthreads();

        // ---- var phase: all contiguous/local ----
        u64 t0 = s_tl[3 * tid], t1 = s_tl[3 * tid + 1], t2 = s_tl[3 * tid + 2];
        if (li < 4) {
            // output li at offsets 4T,3T,2T,1T: sigmoid(ln2*(t0+t1+t2) + llr)
            {
                u64 arg = fma2(ln2p, add2(add2(t0, t1), t2), llrp);
                float ax, ay; upk(arg, ax, ay);
                size_t off = (size_t)(4 - li) * TOT + b0 * NV;
                out[off + tid]      = sigmoidf(ax);
                out[off + NV + tid] = sigmoidf(ay);
            }
            // VN update (log2 domain), packed FMAs, scalar exp2
            float2 w0 = g_ws[li][3 * tid];
            float2 w1 = g_ws[li][3 * tid + 1];
            float2 w2 = g_ws[li][3 * tid + 2];
            u64 a0 = fma2(pk(w0.x, w0.x), t1, fma2(pk(w0.y, w0.y), t2, llr2p));
            u64 a1 = fma2(pk(w1.x, w1.x), t2, fma2(pk(w1.y, w1.y), t0, llr2p));
            u64 a2 = fma2(pk(w2.x, w2.x), t0, fma2(pk(w2.y, w2.y), t1, llr2p));
            float a0x, a0y, a1x, a1y, a2x, a2y;
            upk(a0, a0x, a0y); upk(a1, a1x, a1y); upk(a2, a2x, a2y);
            s_e[3 * tid]     = pk(exp2f(fminf(a0x, VC2)), exp2f(fminf(a0y, VC2)));
            s_e[3 * tid + 1] = pk(exp2f(fminf(a1x, VC2)), exp2f(fminf(a1y, VC2)));
            s_e[3 * tid + 2] = pk(exp2f(fminf(a2x, VC2)), exp2f(fminf(a2y, VC2)));
            __syncthreads();
        } else {
            // final output (offset 0): W9-weighted message sum
            float w90 = g_w9[tid][0], w91 = g_w9[tid][1], w92 = g_w9[tid][2];
            u64 s = fma2(pk(w90, w90), t0,
                    fma2(pk(w91, w91), t1, mul2(pk(w92, w92), t2)));
            u64 arg = fma2(ln2p, s, llrp);
            float ax, ay; upk(arg, ax, ay);
            size_t off = b0 * NV;
            out[off + tid]      = sigmoidf(ax);
            out[off + NV + tid] = sigmoidf(ay);
        }
    }
}

// ---------------- launch ----------------
extern "C" void kernel_launch(void* const* d_in, const int* in_sizes, int n_in,
                              void* d_out, int out_size) {
    // metadata order: x, M_first, M_cn, M_out, bias_matrix, W1, W3, W5, W7, W9, B0..B4
    const float* x     = (const float*)d_in[0];
    const float* M_out = (const float*)d_in[3];
    const float* W1    = (const float*)d_in[5];
    const float* W3    = (const float*)d_in[6];
    const float* W5    = (const float*)d_in[7];
    const float* W7    = (const float*)d_in[8];
    const float* W9    = (const float*)d_in[9];

    prep1<<<(SCAN4 + 255) / 256, 256>>>((const float4*)M_out);
    prep2<<<(12 * NV + 255) / 256, 256>>>(W1, W3, W5, W7, W9);
    bp_main<<<BATCH / ROWS, THREADS>>>(x, (float*)d_out);
}